// round 14
// baseline (speedup 1.0000x reference)
#include <cuda_runtime.h>
#include <math.h>

// Problem dims
#define Bq   32
#define Sq   256
#define Iq   128
#define Hq   512
#define Cq   64
#define BUFD 17
#define OUTL 64

#define NCTA 128      // 4 groups x 32 CTAs
#define GCTA 32       // CTAs per group
#define RB   8        // batches per group
#define NTHR 256
#define WSTRIDE 516   // weight col stride (floats); j-stride 6192B -> conflict-free
#define WVECS 48      // 16 h-cols * 3 outputs
#define QOFF (WVECS * WSTRIDE + 4)   // 24772: Q-variant block offset

// ---------------- device globals ----------------
__device__ __align__(16) float g_Pt[Hq * Hq];        // W_pass @ W_tau
__device__ __align__(16) float g_Pm[Hq * Hq];        // W_pass @ W_mem
__device__ __align__(16) float g_bc[Hq];             // b_in @ W_pass + b_pass
__device__ __align__(16) float g_WE[2 * Hq * 3 * Hq];// [(v*512+col)*3+o][k] col-major weight sets
__device__ __align__(16) float g_MX[2 * Iq * 2048];  // x-side matrices, [v][k][col*4+o]
__device__ __align__(16) float g_bias4[2 * 2048];    // folded biases, [v][col*4+o]
__device__ __align__(16) float g_XW[(size_t)Bq * Sq * 2048]; // per-(b,t) precomputed terms
__device__ __align__(16) float g_h0[2 * Bq * Hq];    // double-buffered h0 broadcast
__device__ unsigned g_bar[4 * 4 * 64];               // [group][4 sub-counters], 256B apart

// ---------------- k_pre1: Pt, Pm, bc, zero h0/bar ----------------
__global__ void k_pre1(const float* __restrict__ Wp, const float* __restrict__ Wt,
                       const float* __restrict__ Wm, const float* __restrict__ b_in,
                       const float* __restrict__ b_pass) {
    int blk = blockIdx.x, tid = threadIdx.x;
    if (blk < 512) {
        int id = blk * 256 + tid;          // [0, 131072)
        int mat = id >> 16;                // 0: Pt, 1: Pm
        int m = (id >> 7) & 511;
        int jq = (id & 127) << 2;
        const float* B = mat ? Wm : Wt;
        float4 acc = make_float4(0.f, 0.f, 0.f, 0.f);
#pragma unroll 4
        for (int u = 0; u < Hq; ++u) {
            float a = __ldg(Wp + m * Hq + u);
            float4 w = __ldg((const float4*)(B + u * Hq + jq));
            acc.x = fmaf(a, w.x, acc.x); acc.y = fmaf(a, w.y, acc.y);
            acc.z = fmaf(a, w.z, acc.z); acc.w = fmaf(a, w.w, acc.w);
        }
        *(float4*)((mat ? g_Pm : g_Pt) + m * Hq + jq) = acc;
    } else if (blk < 520) {
        int id = (blk - 512) * 256 + tid;  // [0, 2048): zero both h0 parities
        float4 z = make_float4(0.f, 0.f, 0.f, 0.f);
#pragma unroll
        for (int q = 0; q < 4; ++q) ((float4*)g_h0)[id * 4 + q] = z;
        if (blk == 512 && tid < 256)
            ((uint4*)g_bar)[tid] = make_uint4(0u, 0u, 0u, 0u);   // 1024 uints
    } else {                               // blk == 520: bc
        for (int c = tid; c < Hq; c += 256) {
            float acc = __ldg(b_pass + c);
            for (int u = 0; u < Hq; ++u)
                acc = fmaf(__ldg(b_in + u), __ldg(Wp + u * Hq + c), acc);
            g_bc[c] = acc;
        }
    }
}

// ---------------- k_pre2: WE (6 weight sets), MX, bias4 ----------------
__global__ void k_pre2(const float* __restrict__ Win, const float* __restrict__ Wp,
                       const float* __restrict__ Wt, const float* __restrict__ Wm,
                       const float* __restrict__ b_in, const float* __restrict__ b_tau,
                       const float* __restrict__ b_mem) {
    int blk = blockIdx.x, tid = threadIdx.x;
    if (blk < 1536) {
        int id = blk * 256 + tid;          // [0, 393216)
        int vo = id >> 16;                 // 0..5 = v*3+o
        int k = (id >> 7) & 511;
        int jq = (id & 127) << 2;
        int v = vo / 3, o = vo % 3;
        float o4[4];
        if (vo == 3) {
            float4 w = __ldg((const float4*)(Win + k * Hq + jq));
            o4[0] = w.x; o4[1] = w.y; o4[2] = w.z; o4[3] = w.w;
        } else {
            const float* X = (vo == 0) ? Wp : (vo == 1) ? g_Pt : (vo == 2) ? g_Pm
                             : (vo == 4) ? Wt : Wm;
            float4 acc = make_float4(0.f, 0.f, 0.f, 0.f);
#pragma unroll 4
            for (int m = 0; m < Hq; ++m) {
                float a = __ldg(Win + k * Hq + m);
                float4 w = __ldg((const float4*)(X + m * Hq + jq));
                acc.x = fmaf(a, w.x, acc.x); acc.y = fmaf(a, w.y, acc.y);
                acc.z = fmaf(a, w.z, acc.z); acc.w = fmaf(a, w.w, acc.w);
            }
            o4[0] = acc.x; o4[1] = acc.y; o4[2] = acc.z; o4[3] = acc.w;
        }
#pragma unroll
        for (int u = 0; u < 4; ++u)
            g_WE[(((v * Hq + jq + u) * 3 + o) << 9) + k] = o4[u];
    } else if (blk < 1920) {
        int id = (blk - 1536) * 256 + tid; // [0, 98304)
        int vo = id >> 14;
        int k = (id >> 7) & 127;
        int jq = (id & 127) << 2;
        int v = vo / 3, o = vo % 3;
        float o4[4];
        if (vo == 3) {
            float4 w = __ldg((const float4*)(Win + (Hq + k) * Hq + jq));
            o4[0] = w.x; o4[1] = w.y; o4[2] = w.z; o4[3] = w.w;
        } else {
            const float* X = (vo == 0) ? Wp : (vo == 1) ? g_Pt : (vo == 2) ? g_Pm
                             : (vo == 4) ? Wt : Wm;
            float4 acc = make_float4(0.f, 0.f, 0.f, 0.f);
#pragma unroll 4
            for (int m = 0; m < Hq; ++m) {
                float a = __ldg(Win + (Hq + k) * Hq + m);
                float4 w = __ldg((const float4*)(X + m * Hq + jq));
                acc.x = fmaf(a, w.x, acc.x); acc.y = fmaf(a, w.y, acc.y);
                acc.z = fmaf(a, w.z, acc.z); acc.w = fmaf(a, w.w, acc.w);
            }
            o4[0] = acc.x; o4[1] = acc.y; o4[2] = acc.z; o4[3] = acc.w;
        }
#pragma unroll
        for (int u = 0; u < 4; ++u)
            g_MX[((v * Iq + k) << 11) + ((jq + u) << 2) + o] = o4[u];
    } else {
        for (int i = tid; i < 4096; i += 256) {
            int v = i >> 11, c = i & 2047, jg = c >> 2, o = c & 3;
            float val = 0.f;
            if (o == 0) {
                val = v ? __ldg(b_in + jg) : g_bc[jg];
            } else if (o < 3) {
                const float* G = (o == 1) ? Wt : Wm;
                float acc = (o == 1) ? __ldg(b_tau + jg) : __ldg(b_mem + jg);
                for (int m = 0; m < Hq; ++m) {
                    float bv = v ? __ldg(b_in + m) : g_bc[m];
                    acc = fmaf(bv, __ldg(G + m * Hq + jg), acc);
                }
                val = acc;
            }
            g_bias4[(v << 11) + c] = val;
        }
    }
}

// ---------------- k_xw ----------------
__global__ void k_xw(const float* __restrict__ x, const int* __restrict__ lengths) {
    __shared__ float sh_x[64 * 129];
    int tid = threadIdx.x;
    int sb0 = blockIdx.x * 64;
    int cq0 = blockIdx.y * 4;
    for (int idx = tid; idx < 64 * 128; idx += 256) {
        int sl = idx >> 7, i = idx & 127;
        sh_x[sl * 129 + i] = x[(sb0 + sl) * Iq + i];
    }
    __syncthreads();
    int cql = tid >> 6, sl = tid & 63;
    int sb = sb0 + sl;
    int b = sb >> 8, t = sb & 255;
    int v = (t < __ldg(lengths + b)) ? 0 : 1;
    int cq = (cq0 + cql) << 2;
    float4 acc = __ldg((const float4*)(g_bias4 + (v << 11) + cq));
#pragma unroll 4
    for (int i = 0; i < Iq; ++i) {
        float a = sh_x[sl * 129 + i];
        float4 w = __ldg((const float4*)(g_MX + ((v * Iq + i) << 11) + cq));
        acc.x = fmaf(a, w.x, acc.x); acc.y = fmaf(a, w.y, acc.y);
        acc.z = fmaf(a, w.z, acc.z); acc.w = fmaf(a, w.w, acc.w);
    }
    *(float4*)(g_XW + ((size_t)sb << 11) + cq) = acc;
}

// ---------------- persistent RNN kernel ----------------

// 4 sub-counters, 256B apart; release-arrive, relaxed batched poll, acquire re-read
__device__ __forceinline__ void grid_barrier(unsigned* base, int sub, unsigned target) {
    __syncthreads();
    if (threadIdx.x == 0) {
        asm volatile("red.release.gpu.global.add.u32 [%0], %1;"
                     :: "l"(base + (sub << 6)), "r"(1u) : "memory");
        unsigned s;
        do {
            unsigned v0, v1, v2, v3;
            asm volatile("ld.relaxed.gpu.global.u32 %0, [%1];" : "=r"(v0) : "l"(base +   0) : "memory");
            asm volatile("ld.relaxed.gpu.global.u32 %0, [%1];" : "=r"(v1) : "l"(base +  64) : "memory");
            asm volatile("ld.relaxed.gpu.global.u32 %0, [%1];" : "=r"(v2) : "l"(base + 128) : "memory");
            asm volatile("ld.relaxed.gpu.global.u32 %0, [%1];" : "=r"(v3) : "l"(base + 192) : "memory");
            s = v0 + v1 + v2 + v3;
        } while (s < target);
        unsigned d;
        asm volatile("ld.acquire.gpu.global.u32 %0, [%1];" : "=r"(d) : "l"(base) : "memory");
    }
    __syncthreads();
}

// smem layout (floats)
#define SH_IN   0        // 8*516 = 4128
#define SH_RED  4128     // 1024 (slot .w reused for decode out-partials)
#define SH_BIAS 5152     // 64
#define SH_WO   5216     // 1024 (2 out cols x 512)
#define SH_W    6240     // 2*24772 = 49544
#define SH_DB   55784    // 128*17 = 2176
#define SM_FLOATS 57960  // 231840 bytes

// fused 3-output GEMM partials: thread (r, j, kc), K=256 per thread
__device__ __forceinline__ void gemm3(const float* sh_in, const float* wbase,
                                      float* sh_red, int r, int j, int kc) {
    const float* ap = sh_in + r * WSTRIDE + (kc << 8);
    const float* w0 = wbase + (kc << 8);
    const float* w1 = w0 + WSTRIDE;
    const float* w2 = w0 + 2 * WSTRIDE;
    float a0 = 0.f, a1 = 0.f, a2 = 0.f;
#pragma unroll 8
    for (int k = 0; k < 256; k += 4) {
        float4 a = *(const float4*)(ap + k);
        float4 u = *(const float4*)(w0 + k);
        float4 v = *(const float4*)(w1 + k);
        float4 w = *(const float4*)(w2 + k);
        a0 = fmaf(a.x, u.x, a0); a0 = fmaf(a.y, u.y, a0);
        a0 = fmaf(a.z, u.z, a0); a0 = fmaf(a.w, u.w, a0);
        a1 = fmaf(a.x, v.x, a1); a1 = fmaf(a.y, v.y, a1);
        a1 = fmaf(a.z, v.z, a1); a1 = fmaf(a.w, v.w, a1);
        a2 = fmaf(a.x, w.x, a2); a2 = fmaf(a.y, w.y, a2);
        a2 = fmaf(a.z, w.z, a2); a2 = fmaf(a.w, w.w, a2);
    }
    int s = ((j * 8 + r) << 3) + (kc << 2);
    sh_red[s] = a0; sh_red[s + 1] = a1; sh_red[s + 2] = a2;
}

__global__ void __launch_bounds__(NTHR, 1) k_rnn(const int* __restrict__ lengths,
                                                 const float* __restrict__ W_out,
                                                 const float* __restrict__ b_out,
                                                 float* __restrict__ out) {
    extern __shared__ float sm[];
    float* sh_in   = sm + SH_IN;
    float* sh_red  = sm + SH_RED;
    float* sh_bias = sm + SH_BIAS;
    float* sh_wo   = sm + SH_WO;
    float* sh_w    = sm + SH_W;
    float* sh_db   = sm + SH_DB;
    int tid = threadIdx.x, cta = blockIdx.x;
    int grp = cta >> 5, cg = cta & 31;
    int b0 = grp * RB;
    int jg0 = cg * 16;
    unsigned* bar = g_bar + grp * 256;
    int sub = cg & 3;
    int r = tid & 7, j = (tid >> 3) & 15, kc = tid >> 7;

    // ---- preload: weight slices (both variants), biases, W_out cols, zero dbuf ----
    for (int i = tid; i < 12288; i += NTHR) {   // 12288 float4 = 2 x 48 x 128
        int v = i / 6144, rem = (i >> 7) % 48, kq = (i & 127) << 2;
        *(float4*)(sh_w + v * QOFF + rem * WSTRIDE + kq) =
            *(const float4*)(g_WE + (((v * Hq + jg0 + rem / 3) * 3 + rem % 3) << 9) + kq);
    }
    if (tid < 64) sh_bias[tid] = g_bias4[(jg0 << 2) + tid];      // P-variant decode bias
    for (int k = tid; k < Hq; k += NTHR) {
        sh_wo[k]       = __ldg(W_out + k * Cq + cg * 2);
        sh_wo[512 + k] = __ldg(W_out + k * Cq + cg * 2 + 1);
    }
    for (int i = tid; i < 128 * BUFD; i += NTHR) sh_db[i] = 0.f;
    int lenr = __ldg(lengths + b0 + r);
    float bo0 = __ldg(b_out + cg * 2), bo1 = __ldg(b_out + cg * 2 + 1);
    __syncthreads();

    unsigned nb = 0;
    int par = 0;

    // ---- encode: 256 steps, ONE barrier each ----
    for (int t = 0; t < Sq; ++t) {
        const float* src = g_h0 + par * (Bq * Hq) + b0 * Hq;
        float4 xw = make_float4(0.f, 0.f, 0.f, 0.f);
        if (tid < 128) {
            int bb = tid & 7, hc = tid >> 3;
            xw = __ldcg((const float4*)(g_XW + (((size_t)(b0 + bb) * Sq + t) << 11)
                                        + ((jg0 + hc) << 2)));
        }
        // stage h0 (rotated start per CTA to spread L2 slices)
        for (int i = tid; i < 1024; i += NTHR) {
            int i2 = (i + (cg << 5)) & 1023;
            int bb = i2 >> 7, h4 = (i2 & 127) << 2;
            *(float4*)(sh_in + bb * WSTRIDE + h4) =
                __ldcg((const float4*)(src + bb * Hq + h4));
        }
        __syncthreads();

        gemm3(sh_in, sh_w + ((t < lenr) ? 0 : QOFF) + (j * 3) * WSTRIDE,
              sh_red, r, j, kc);
        __syncthreads();

        if (tid < 128) {
            int bb = tid & 7, hc = tid >> 3;
            int s8 = ((hc * 8 + bb) << 3);
            float h  = sh_red[s8]     + sh_red[s8 + 4] + xw.x;
            float ti = sh_red[s8 + 1] + sh_red[s8 + 5] + xw.y;
            float mi = sh_red[s8 + 2] + sh_red[s8 + 6] + xw.z;
            float tau = __fdividef(16.f, 1.f + __expf(-ti));
            tau = fminf(fmaxf(tau, 1.f), 16.f);
            float mem = __fdividef(1.f, 1.f + __expf(-mi));
            float* dp = sh_db + tid * BUFD;
#pragma unroll
            for (int d = 0; d < 16; ++d) {
                float wq = __fdividef(mem, 1.f + fabsf(tau - (float)(d + 1)));
                dp[d] = fmaf(wq, h, dp[d + 1]);
            }
            dp[16] = 0.f;
            __stcg(g_h0 + (par ^ 1) * (Bq * Hq) + (b0 + bb) * Hq + jg0 + hc, dp[0]);
        }
        nb++; grid_barrier(bar, sub, nb * GCTA);
        par ^= 1;
    }

    // ---- decode: 64 steps (P-variant; 2 out cols per CTA in red slot .w) ----
    int r2 = tid & 7, seg = (tid >> 3) & 15, oc = tid >> 7;
    for (int t = 0; t < OUTL; ++t) {
        const float* src = g_h0 + par * (Bq * Hq) + b0 * Hq;
        for (int i = tid; i < 1024; i += NTHR) {
            int i2 = (i + (cg << 5)) & 1023;
            int bb = i2 >> 7, h4 = (i2 & 127) << 2;
            *(float4*)(sh_in + bb * WSTRIDE + h4) =
                __ldcg((const float4*)(src + bb * Hq + h4));
        }
        __syncthreads();

        gemm3(sh_in, sh_w + (j * 3) * WSTRIDE, sh_red, r, j, kc);
        {   // out-col partial: (r2, seg, oc): 32 k
            const float* ap2 = sh_in + r2 * WSTRIDE + seg * 32;
            const float* wp2 = sh_wo + oc * 512 + seg * 32;
            float aco = 0.f;
#pragma unroll 8
            for (int k = 0; k < 32; ++k) aco = fmaf(ap2[k], wp2[k], aco);
            sh_red[((seg * 8 + r2) << 3) + (oc << 2) + 3] = aco;
        }
        __syncthreads();

        if (tid < 128) {
            int bb = tid & 7, hc = tid >> 3;
            int s8 = ((hc * 8 + bb) << 3), j4 = hc << 2;
            float h  = sh_red[s8]     + sh_red[s8 + 4] + sh_bias[j4];
            float ti = sh_red[s8 + 1] + sh_red[s8 + 5] + sh_bias[j4 + 1];
            float mi = sh_red[s8 + 2] + sh_red[s8 + 6] + sh_bias[j4 + 2];
            float tau = __fdividef(16.f, 1.f + __expf(-ti));
            tau = fminf(fmaxf(tau, 1.f), 16.f);
            float mem = __fdividef(1.f, 1.f + __expf(-mi));
            float* dp = sh_db + tid * BUFD;
#pragma unroll
            for (int d = 0; d < 16; ++d) {
                float wq = __fdividef(mem, 1.f + fabsf(tau - (float)(d + 1)));
                dp[d] = fmaf(wq, h, dp[d + 1]);
            }
            dp[16] = 0.f;
            __stcg(g_h0 + (par ^ 1) * (Bq * Hq) + (b0 + bb) * Hq + jg0 + hc, dp[0]);
        } else if (tid < 144) {
            int rr = (tid - 128) & 7, oo = (tid - 128) >> 3;
            float sv = oo ? bo1 : bo0;
#pragma unroll
            for (int ss = 0; ss < 16; ++ss)
                sv += sh_red[((ss * 8 + rr) << 3) + (oo << 2) + 3];
            out[(b0 + rr) * (OUTL * Cq) + t * Cq + cg * 2 + oo] = sv;
        }
        nb++; grid_barrier(bar, sub, nb * GCTA);
        par ^= 1;
    }
}

// ---------------- launch ----------------
extern "C" void kernel_launch(void* const* d_in, const int* in_sizes, int n_in,
                              void* d_out, int out_size) {
    const float* x       = (const float*)d_in[0];
    const int*   lengths = (const int*)d_in[1];
    int wi = 2;
    if (n_in >= 13 && in_sizes[2] == 1) wi = 3;
    const float* W_in   = (const float*)d_in[wi + 0];
    const float* b_in   = (const float*)d_in[wi + 1];
    const float* W_pass = (const float*)d_in[wi + 2];
    const float* b_pass = (const float*)d_in[wi + 3];
    const float* W_tau  = (const float*)d_in[wi + 4];
    const float* b_tau  = (const float*)d_in[wi + 5];
    const float* W_mem  = (const float*)d_in[wi + 6];
    const float* b_mem  = (const float*)d_in[wi + 7];
    const float* W_out  = (const float*)d_in[wi + 8];
    const float* b_out  = (const float*)d_in[wi + 9];
    float* out = (float*)d_out;

    static int smem_set = 0;
    const int smem_bytes = SM_FLOATS * (int)sizeof(float);   // 231840
    if (!smem_set) {
        cudaFuncSetAttribute(k_rnn, cudaFuncAttributeMaxDynamicSharedMemorySize, smem_bytes);
        smem_set = 1;
    }

    k_pre1<<<521, 256>>>(W_pass, W_tau, W_mem, b_in, b_pass);
    k_pre2<<<1921, 256>>>(W_in, W_pass, W_tau, W_mem, b_in, b_tau, b_mem);
    k_xw<<<dim3(128, 128), 256>>>(x, lengths);
    k_rnn<<<NCTA, NTHR, smem_bytes>>>(lengths, W_out, b_out, out);
}

// round 15
// speedup vs baseline: 1.1809x; 1.1809x over previous
#include <cuda_runtime.h>
#include <math.h>

// Problem dims
#define Bq   32
#define Sq   256
#define Iq   128
#define Hq   512
#define Cq   64
#define BUFD 17
#define OUTL 64

#define NCTA 128      // 4 groups x 32 CTAs
#define GCTA 32       // CTAs per group
#define RB   8        // batches per group
#define NTHR 256
#define SHS  516      // padded smem activation row stride (floats)

// ---------------- device globals ----------------
__device__ __align__(16) float g_WAh[Hq * 1024];      // [W_in | W_in@W_pass], col-interleaved
__device__ __align__(16) float g_WCx[Iq * 1024];      // x-rows, same interleave
__device__ __align__(16) float g_WB [Hq * 1024];      // [W_tau | W_mem] col-interleaved
__device__ __align__(16) float g_WD [Hq * 576];       // decode: 0..511 = W_comb, 512..575 = W_out
__device__ __align__(16) float g_bA [1024];
__device__ __align__(16) float g_bB [1024];
__device__ __align__(16) float g_bD [576];
__device__ __align__(16) float g_XW [Sq * Bq * 1024]; // x @ [Wi_x | Wi_x Wp], [(b*256+t)][1024]
__device__ __align__(16) float g_hbuf[Bq * Hq];       // h broadcast (stage A -> B)
__device__ __align__(16) float g_h0  [Bq * Hq];       // plane-0 broadcast (stage B -> next A)
__device__ unsigned g_bar[4 * 4 * 64];                // [group][4 sub-counters], 256B apart

// ---------------- fused precompute kernel ----------------
// blocks: [0,320) comb | [320,1344) WB+Wout | 1344 bias | [1345,1361) zero h0/bar
__global__ void k_pre(const float* __restrict__ W_in, const float* __restrict__ W_pass,
                      const float* __restrict__ W_tau, const float* __restrict__ W_mem,
                      const float* __restrict__ W_out,
                      const float* __restrict__ b_in, const float* __restrict__ b_pass,
                      const float* __restrict__ b_tau, const float* __restrict__ b_mem,
                      const float* __restrict__ b_out) {
    int blk = blockIdx.x, tid = threadIdx.x;
    if (blk < 320) {
        int id = blk * 256 + tid;          // 81920 threads
        int k  = id >> 7;                  // 0..639 (warp-uniform)
        int cq = id & 127;                 // col quad
        float4 acc = make_float4(0.f, 0.f, 0.f, 0.f);
        for (int j = 0; j < Hq; ++j) {
            float a  = __ldg(W_in + k * Hq + j);
            float4 w = __ldg((const float4*)(W_pass + j * Hq + cq * 4));
            acc.x = fmaf(a, w.x, acc.x);
            acc.y = fmaf(a, w.y, acc.y);
            acc.z = fmaf(a, w.z, acc.z);
            acc.w = fmaf(a, w.w, acc.w);
        }
        float aw[4] = {acc.x, acc.y, acc.z, acc.w};
        if (k < Hq) {
            int base = k * 1024;
#pragma unroll
            for (int v = 0; v < 4; ++v) {
                int c = cq * 4 + v;
                g_WAh[base + 2 * c]     = W_in[k * Hq + c];
                g_WAh[base + 2 * c + 1] = aw[v];
            }
            *(float4*)(g_WD + k * 576 + cq * 4) = acc;
        } else {
            int base = (k - Hq) * 1024;
#pragma unroll
            for (int v = 0; v < 4; ++v) {
                int c = cq * 4 + v;
                g_WCx[base + 2 * c]     = W_in[k * Hq + c];
                g_WCx[base + 2 * c + 1] = aw[v];
            }
        }
    } else if (blk < 1344) {
        int id = (blk - 320) * 256 + tid;  // 0..262143
        int k = id >> 9, c = id & 511;
        g_WB[k * 1024 + 2 * c]     = W_tau[k * Hq + c];
        g_WB[k * 1024 + 2 * c + 1] = W_mem[k * Hq + c];
        if (id < Hq * Cq) {
            int k2 = id >> 6, c2 = id & 63;
            g_WD[k2 * 576 + 512 + c2] = W_out[k2 * Cq + c2];
        }
    } else if (blk == 1344) {
#pragma unroll
        for (int hh = 0; hh < 2; ++hh) {
            int c = tid + hh * 256;
            float acc = b_pass[c];
            for (int j = 0; j < Hq; ++j) acc = fmaf(b_in[j], W_pass[j * Hq + c], acc);
            g_bA[2 * c]     = b_in[c];
            g_bA[2 * c + 1] = acc;
            g_bD[c]         = acc;
            g_bB[2 * c]     = b_tau[c];
            g_bB[2 * c + 1] = b_mem[c];
            if (c < Cq) g_bD[512 + c] = b_out[c];
        }
    } else {
        int id = (blk - 1345) * 256 + tid;  // 0..4095 -> g_h0 (4096 float4)
        ((float4*)g_h0)[id] = make_float4(0.f, 0.f, 0.f, 0.f);
        if (blk == 1345 && tid < 256)
            ((uint4*)g_bar)[tid] = make_uint4(0u, 0u, 0u, 0u);   // whole g_bar
    }
}

// XW[(b*256+t)][col] = sum_i x[b][t][i] * WCx[i][col]
__global__ void k_xw(const float* __restrict__ x) {
    __shared__ float sh_x[64 * 129];
    int tid = threadIdx.x;
    int sb0 = blockIdx.x * 64;
    int cq0 = blockIdx.y * 4;
    for (int idx = tid; idx < 64 * 128; idx += NTHR) {
        int sl = idx >> 7, i = idx & 127;
        sh_x[sl * 129 + i] = x[(sb0 + sl) * Iq + i];
    }
    __syncthreads();
    int cql = tid >> 6, sl = tid & 63;
    int cq = cq0 + cql;
    float4 acc = make_float4(0.f, 0.f, 0.f, 0.f);
#pragma unroll 4
    for (int i = 0; i < Iq; ++i) {
        float a = sh_x[sl * 129 + i];
        float4 w = __ldg((const float4*)(g_WCx + i * 1024 + cq * 4));
        acc.x = fmaf(a, w.x, acc.x);
        acc.y = fmaf(a, w.y, acc.y);
        acc.z = fmaf(a, w.z, acc.z);
        acc.w = fmaf(a, w.w, acc.w);
    }
    *(float4*)(g_XW + (sb0 + sl) * 1024 + cq * 4) = acc;
}

// ---------------- persistent RNN kernel ----------------

// 4 sub-counters 256B apart; release-arrive, relaxed batched poll, acquire re-read
__device__ __forceinline__ void grid_barrier(unsigned* base, int sub, unsigned target) {
    __syncthreads();
    if (threadIdx.x == 0) {
        asm volatile("red.release.gpu.global.add.u32 [%0], %1;"
                     :: "l"(base + (sub << 6)), "r"(1u) : "memory");
        unsigned s;
        do {
            unsigned v0, v1, v2, v3;
            asm volatile("ld.relaxed.gpu.global.u32 %0, [%1];" : "=r"(v0) : "l"(base +   0) : "memory");
            asm volatile("ld.relaxed.gpu.global.u32 %0, [%1];" : "=r"(v1) : "l"(base +  64) : "memory");
            asm volatile("ld.relaxed.gpu.global.u32 %0, [%1];" : "=r"(v2) : "l"(base + 128) : "memory");
            asm volatile("ld.relaxed.gpu.global.u32 %0, [%1];" : "=r"(v3) : "l"(base + 192) : "memory");
            s = v0 + v1 + v2 + v3;
        } while (s < target);
        unsigned d;
        asm volatile("ld.acquire.gpu.global.u32 %0, [%1];" : "=r"(d) : "l"(base) : "memory");
    }
    __syncthreads();
}

// stage RB x 512 activation rows into padded smem, CTA-rotated start
__device__ __forceinline__ void stage_load(float* sh_in, const float* __restrict__ src, int cg) {
    int tid = threadIdx.x;
#pragma unroll
    for (int i = tid; i < 1024; i += NTHR) {
        int i2 = (i + (cg << 5)) & 1023;
        int b = i2 >> 7, h4 = (i2 & 127) << 2;
        *(float4*)(sh_in + b * SHS + h4) = __ldcg((const float4*)(src + b * Hq + h4));
    }
}

// GEMM partials: 8 rows x NC cols, K=512; weights row-major stride NC in smem.
// thread map: r=tid&7, q=(tid>>3)&7, kc=tid>>6 (warp-uniform kc; q uniform per 8-lane phase).
template<int NC>
__device__ __forceinline__ void gemm_part(const float* __restrict__ ws,
                                          const float* sh_in, float* sh_red,
                                          int r, int q, int kc) {
    constexpr int NQ = NC / 4;
    if (q < NQ) {
        const float* wp = ws + (kc * 128) * NC + q * 4;
        const float* ap = sh_in + r * SHS + kc * 128;
        float4 acc = make_float4(0.f, 0.f, 0.f, 0.f);
#pragma unroll 4
        for (int k = 0; k < 128; k += 4) {
            float4 a  = *(const float4*)(ap + k);
            float4 w0 = *(const float4*)(wp + (k + 0) * NC);
            float4 w1 = *(const float4*)(wp + (k + 1) * NC);
            float4 w2 = *(const float4*)(wp + (k + 2) * NC);
            float4 w3 = *(const float4*)(wp + (k + 3) * NC);
            acc.x = fmaf(a.x, w0.x, acc.x); acc.y = fmaf(a.x, w0.y, acc.y);
            acc.z = fmaf(a.x, w0.z, acc.z); acc.w = fmaf(a.x, w0.w, acc.w);
            acc.x = fmaf(a.y, w1.x, acc.x); acc.y = fmaf(a.y, w1.y, acc.y);
            acc.z = fmaf(a.y, w1.z, acc.z); acc.w = fmaf(a.y, w1.w, acc.w);
            acc.x = fmaf(a.z, w2.x, acc.x); acc.y = fmaf(a.z, w2.y, acc.y);
            acc.z = fmaf(a.z, w2.z, acc.z); acc.w = fmaf(a.z, w2.w, acc.w);
            acc.x = fmaf(a.w, w3.x, acc.x); acc.y = fmaf(a.w, w3.y, acc.y);
            acc.z = fmaf(a.w, w3.z, acc.z); acc.w = fmaf(a.w, w3.w, acc.w);
        }
        ((float4*)sh_red)[(q * 4 + kc) * 8 + r] = acc;
    }
}

// sum 4 kc partials for (rr, col-quad qq)
__device__ __forceinline__ float4 red4(const float* sh_red, int rr, int qq) {
    float4 s0 = ((const float4*)sh_red)[(qq * 4 + 0) * 8 + rr];
    float4 s1 = ((const float4*)sh_red)[(qq * 4 + 1) * 8 + rr];
    float4 s2 = ((const float4*)sh_red)[(qq * 4 + 2) * 8 + rr];
    float4 s3 = ((const float4*)sh_red)[(qq * 4 + 3) * 8 + rr];
    return make_float4(s0.x + s1.x + s2.x + s3.x, s0.y + s1.y + s2.y + s3.y,
                       s0.z + s1.z + s2.z + s3.z, s0.w + s1.w + s2.w + s3.w);
}

// smem layout (floats)
#define SH_IN   0        // 8*516 = 4128
#define SH_RED  4128     // 1024
#define SH_BIAS 5152     // 96 (A:32 | B:32 | D:24+pad)
#define SH_DB   5248     // 128*17 = 2176
#define SH_WA   7424     // 16384
#define SH_WB   23808    // 16384
#define SM_FLOATS 40192  // 160768 bytes

__global__ void __launch_bounds__(NTHR, 1) k_rnn(const int* __restrict__ lengths,
                                                 float* __restrict__ out) {
    extern __shared__ float sm[];
    float* sh_in   = sm + SH_IN;
    float* sh_red  = sm + SH_RED;
    float* sh_bias = sm + SH_BIAS;
    float* sh_db   = sm + SH_DB;
    float* sh_wA   = sm + SH_WA;
    float* sh_wB   = sm + SH_WB;
    int tid = threadIdx.x, cta = blockIdx.x;
    int grp = cta >> 5, cg = cta & 31;
    int b0 = grp * RB;
    int scol0 = cg * 32;        // interleaved col base (stages A/B)
    int hcol0 = cg * 16;        // h col base
    unsigned* bar = g_bar + grp * 256;
    int sub = cg & 3;
    int r = tid & 7, q = (tid >> 3) & 7, kc = tid >> 6;
    int rr = tid & 7, qq = tid >> 3;    // reduction map (tid < 64)

    // ---- preload weight slices + biases; zero local delay buffer ----
#pragma unroll
    for (int i = tid; i < 4096; i += NTHR) {
        int k = i >> 3, c4 = (i & 7) * 4;
        ((float4*)sh_wA)[i] = *(const float4*)(g_WAh + k * 1024 + scol0 + c4);
        ((float4*)sh_wB)[i] = *(const float4*)(g_WB  + k * 1024 + scol0 + c4);
    }
    if (tid < 32) {
        sh_bias[tid]      = g_bA[scol0 + tid];
        sh_bias[32 + tid] = g_bB[scol0 + tid];
        if (cg < 24 && tid < 24) sh_bias[64 + tid] = g_bD[cg * 24 + tid];
    }
    for (int i = tid; i < 128 * BUFD; i += NTHR) sh_db[i] = 0.f;
    int lenA = __ldg(lengths + b0 + rr);   // valid where used (tid<64)
    __syncthreads();

    unsigned nb = 0;

    // ---- encode: 256 steps ----
    for (int t = 0; t < Sq; ++t) {
        // stage A: h0 @ [W_in | W_comb] + XW_t -> h (publish to g_hbuf)
        float4 xw4 = make_float4(0.f, 0.f, 0.f, 0.f);
        if (tid < 64)
            xw4 = __ldcg((const float4*)(g_XW + ((b0 + rr) * Sq + t) * 1024
                                         + scol0 + qq * 4));
        stage_load(sh_in, g_h0 + b0 * Hq, cg);
        __syncthreads();
        gemm_part<32>(sh_wA, sh_in, sh_red, r, q, kc);
        __syncthreads();
        if (tid < 64) {
            float4 s = red4(sh_red, rr, qq);
            float4 bb = *(const float4*)(sh_bias + qq * 4);
            float h1a = s.x + bb.x + xw4.x, pa = s.y + bb.y + xw4.y;
            float h1b = s.z + bb.z + xw4.z, pb = s.w + bb.w + xw4.w;
            bool m = (t < lenA);
            float2 hv = make_float2(m ? pa : h1a, m ? pb : h1b);
            *(float2*)&hv;  // keep as value
            float2* dst = (float2*)(g_hbuf + (b0 + rr) * Hq + hcol0 + qq * 2);
            __stcg((float2*)dst, hv);
        }
        nb++; grid_barrier(bar, sub, nb * GCTA);

        // stage B: h @ [W_tau | W_mem] -> gates; smem delay shift; publish plane 0
        stage_load(sh_in, g_hbuf + b0 * Hq, cg);
        __syncthreads();
        gemm_part<32>(sh_wB, sh_in, sh_red, r, q, kc);
        __syncthreads();
        if (tid < 64) {
            float4 s = red4(sh_red, rr, qq);
            float4 bb = *(const float4*)(sh_bias + 32 + qq * 4);
            float2 h0v;
#pragma unroll
            for (int e = 0; e < 2; ++e) {
                float ti = e ? (s.z + bb.z) : (s.x + bb.x);
                float mi = e ? (s.w + bb.w) : (s.y + bb.y);
                float tau = __fdividef(16.f, 1.f + __expf(-ti));
                tau = fminf(fmaxf(tau, 1.f), 16.f);
                float mem = __fdividef(1.f, 1.f + __expf(-mi));
                int hc = qq * 2 + e;
                float hv = sh_in[rr * SHS + hcol0 + hc];
                float* dp = sh_db + (hc * 8 + rr) * BUFD;
#pragma unroll
                for (int d = 0; d < 16; ++d) {
                    float wq = __fdividef(mem, 1.f + fabsf(tau - (float)(d + 1)));
                    dp[d] = fmaf(wq, hv, dp[d + 1]);
                }
                dp[16] = 0.f;
                (e ? h0v.y : h0v.x) = dp[0];
            }
            __stcg((float2*)(g_h0 + (b0 + rr) * Hq + hcol0 + qq * 2), h0v);
        }
        nb++; grid_barrier(bar, sub, nb * GCTA);
    }

    // ---- reload sh_wA with decode weights (24 cols/CTA for cg<24) ----
    int scol0d = cg * 24;
    if (cg < 24) {
        for (int k = tid; k < Hq; k += NTHR) {
#pragma unroll
            for (int jj = 0; jj < 6; ++jj)
                *(float4*)(sh_wA + k * 24 + jj * 4) =
                    *(const float4*)(g_WD + k * 576 + scol0d + jj * 4);
        }
    }
    __syncthreads();

    // ---- decode: 64 steps ----
    for (int t = 0; t < OUTL; ++t) {
        if (cg < 24) {
            stage_load(sh_in, g_h0 + b0 * Hq, cg);
            __syncthreads();
            gemm_part<24>(sh_wA, sh_in, sh_red, r, q, kc);
            __syncthreads();
            if (tid < 48) {
                float4 s = red4(sh_red, rr, qq);
                float4 bb = *(const float4*)(sh_bias + 64 + qq * 4);
                float4 v = make_float4(s.x + bb.x, s.y + bb.y, s.z + bb.z, s.w + bb.w);
                int sc = scol0d + qq * 4;
                if (sc < Hq)
                    __stcg((float4*)(g_hbuf + (b0 + rr) * Hq + sc), v);
                else
                    *(float4*)(out + (b0 + rr) * (OUTL * Cq) + t * Cq + (sc - Hq)) = v;
            }
        }
        nb++; grid_barrier(bar, sub, nb * GCTA);

        stage_load(sh_in, g_hbuf + b0 * Hq, cg);
        __syncthreads();
        gemm_part<32>(sh_wB, sh_in, sh_red, r, q, kc);
        __syncthreads();
        if (tid < 64) {
            float4 s = red4(sh_red, rr, qq);
            float4 bb = *(const float4*)(sh_bias + 32 + qq * 4);
            float2 h0v;
#pragma unroll
            for (int e = 0; e < 2; ++e) {
                float ti = e ? (s.z + bb.z) : (s.x + bb.x);
                float mi = e ? (s.w + bb.w) : (s.y + bb.y);
                float tau = __fdividef(16.f, 1.f + __expf(-ti));
                tau = fminf(fmaxf(tau, 1.f), 16.f);
                float mem = __fdividef(1.f, 1.f + __expf(-mi));
                int hc = qq * 2 + e;
                float hv = sh_in[rr * SHS + hcol0 + hc];
                float* dp = sh_db + (hc * 8 + rr) * BUFD;
#pragma unroll
                for (int d = 0; d < 16; ++d) {
                    float wq = __fdividef(mem, 1.f + fabsf(tau - (float)(d + 1)));
                    dp[d] = fmaf(wq, hv, dp[d + 1]);
                }
                dp[16] = 0.f;
                (e ? h0v.y : h0v.x) = dp[0];
            }
            __stcg((float2*)(g_h0 + (b0 + rr) * Hq + hcol0 + qq * 2), h0v);
        }
        nb++; grid_barrier(bar, sub, nb * GCTA);
    }
}

// ---------------- launch ----------------
extern "C" void kernel_launch(void* const* d_in, const int* in_sizes, int n_in,
                              void* d_out, int out_size) {
    const float* x       = (const float*)d_in[0];
    const int*   lengths = (const int*)d_in[1];
    int wi = 2;
    if (n_in >= 13 && in_sizes[2] == 1) wi = 3;
    const float* W_in   = (const float*)d_in[wi + 0];
    const float* b_in   = (const float*)d_in[wi + 1];
    const float* W_pass = (const float*)d_in[wi + 2];
    const float* b_pass = (const float*)d_in[wi + 3];
    const float* W_tau  = (const float*)d_in[wi + 4];
    const float* b_tau  = (const float*)d_in[wi + 5];
    const float* W_mem  = (const float*)d_in[wi + 6];
    const float* b_mem  = (const float*)d_in[wi + 7];
    const float* W_out  = (const float*)d_in[wi + 8];
    const float* b_out  = (const float*)d_in[wi + 9];
    float* out = (float*)d_out;

    static int smem_set = 0;
    const int smem_bytes = SM_FLOATS * (int)sizeof(float);   // 160768
    if (!smem_set) {
        cudaFuncSetAttribute(k_rnn, cudaFuncAttributeMaxDynamicSharedMemorySize, smem_bytes);
        smem_set = 1;
    }

    k_pre<<<1361, 256>>>(W_in, W_pass, W_tau, W_mem, W_out,
                         b_in, b_pass, b_tau, b_mem, b_out);
    k_xw<<<dim3(128, 64), 256>>>(x);
    k_rnn<<<NCTA, NTHR, smem_bytes>>>(lengths, out);
}